// round 3
// baseline (speedup 1.0000x reference)
#include <cuda_runtime.h>
#include <math.h>

#define N_TOT  8192
#define NF     8
#define HID    64
#define TILE   8
#define NTHR   128
#define NBLK   (N_TOT / TILE)   // 1024
#define HP2    18               // pitch (floats): 2*TILE + 2 pad, even

typedef unsigned long long ull;

__device__ __forceinline__ float sigm(float x) {
    return 1.0f / (1.0f + __expf(-x));
}

// Accurate tanh: rel err ~1e-6 everywhere (poly near 0).
__device__ __forceinline__ float tanh_acc(float x) {
    float ax = fabsf(x);
    if (ax < 0.0625f) {
        float x2 = x * x;
        return x * (1.0f + x2 * (-0.33333333f + x2 * 0.13333334f));
    }
    float e = __expf(-2.0f * ax);
    float r = (1.0f - e) / (1.0f + e);
    return (x < 0.0f) ? -r : r;
}

// Packed dual-lane FMA (sm_103a FFMA2; ptxas never emits this from C++).
__device__ __forceinline__ ull fma2(ull a, ull b, ull c) {
    ull d;
    asm("fma.rn.f32x2 %0, %1, %2, %3;" : "=l"(d) : "l"(a), "l"(b), "l"(c));
    return d;
}
__device__ __forceinline__ float2 unpack2(ull v) {
    float2 r;
    asm("mov.b64 {%0, %1}, %2;" : "=f"(r.x), "=f"(r.y) : "l"(v));
    return r;
}

// ---------------------------------------------------------------------------
// Single fused kernel: dual MLP (8->64->64->1, tanh) + quadrature reduction
// + MIMICS epilogue. 1024 blocks x 128 threads, 8 samples per block.
// Accumulators packed over hidden-column pairs (fma.rn.f32x2); activations
// stored DUPLICATED (h,h) in smem so the packed a-operand is a single LDS.64.
// 128x32 orientation quadrature collapsed analytically to 3 theta-moments
// (exact: uniform 32-pt phi-sum of cos^k, k<=4, equals the continuous mean),
// computed per block (1 point/thread) and warp-reduced alongside layer 3.
// ---------------------------------------------------------------------------
__global__ __launch_bounds__(NTHR)
void pinn_kernel(const float* __restrict__ X,
                 const float* __restrict__ theta,
                 const float* __restrict__ Wp1, const float* __restrict__ bp1,
                 const float* __restrict__ Wp2, const float* __restrict__ bp2,
                 const float* __restrict__ Wp3, const float* __restrict__ bp3,
                 const float* __restrict__ Wc1, const float* __restrict__ bc1,
                 const float* __restrict__ Wc2, const float* __restrict__ bc2,
                 const float* __restrict__ Wc3, const float* __restrict__ bc3,
                 const float* __restrict__ nb_raw, const float* __restrict__ nl_raw,
                 const float* __restrict__ so_raw, const float* __restrict__ mg_raw,
                 const float* __restrict__ s_raw,
                 float* __restrict__ out) {
    __shared__ float XT2[NF][HP2];                 // duplicated (x,x)
    __shared__ float H1p[HID][HP2], H1c[HID][HP2]; // duplicated (h,h)
    __shared__ float H2p[HID][HP2], H2c[HID][HP2];
    __shared__ float qs[4][NTHR];                  // quadrature partials
    __shared__ float qsum[4];
    __shared__ float Ys[2][TILE];

    const int t = threadIdx.x;
    const int base = blockIdx.x * TILE;
    const float PI = 3.14159265358979f;

    // ---- stage: quadrature point per thread + X (duplicated) ----
    {
        float sig_o = (10.0f + 70.0f * sigm(so_raw[0])) * (PI / 180.0f);
        float th  = (float)t * (PI * 0.5f / 127.0f);   // linspace(0, pi/2, 128)
        float d   = th - PI * 0.25f;
        float pdf = expf(-d * d / (2.0f * sig_o * sig_o)) * sinf(th);
        float c = cosf(th), s = sinf(th);
        float c2 = c * c, s2 = s * s;
        qs[0][t] = pdf;
        qs[1][t] = pdf * c2 * c2;
        qs[2][t] = pdf * c2 * s2;
        qs[3][t] = pdf * s2 * s2;
    }
    if (t < TILE * NF) {
        int r = t >> 3, k = t & 7;
        float x = X[base * NF + t];                    // contiguous
        *(float2*)&XT2[k][2 * r] = make_float2(x, x);
    }
    __syncthreads();

    const int c0 = (t & 15) * 4;   // 4 hidden cols owned
    const int r  = t >> 4;         // 1 sample owned

    ull ap0, ap1, ac0, ac1;        // packed accumulators (col pairs) per MLP

    // ---- layer 1 (both MLPs): K = 8 ----
    {
        ulonglong2 bp = __ldg((const ulonglong2*)(bp1 + c0));
        ulonglong2 bc = __ldg((const ulonglong2*)(bc1 + c0));
        ap0 = bp.x; ap1 = bp.y; ac0 = bc.x; ac1 = bc.y;
        #pragma unroll
        for (int k = 0; k < NF; k++) {
            ull x2 = *(const ull*)&XT2[k][2 * r];
            ulonglong2 wp = __ldg((const ulonglong2*)(Wp1 + k * HID + c0));
            ulonglong2 wc = __ldg((const ulonglong2*)(Wc1 + k * HID + c0));
            ap0 = fma2(x2, wp.x, ap0);
            ap1 = fma2(x2, wp.y, ap1);
            ac0 = fma2(x2, wc.x, ac0);
            ac1 = fma2(x2, wc.y, ac1);
        }
        float2 p0 = unpack2(ap0), p1 = unpack2(ap1);
        float2 q0 = unpack2(ac0), q1 = unpack2(ac1);
        float v;
        v = tanh_acc(p0.x); *(float2*)&H1p[c0 + 0][2 * r] = make_float2(v, v);
        v = tanh_acc(p0.y); *(float2*)&H1p[c0 + 1][2 * r] = make_float2(v, v);
        v = tanh_acc(p1.x); *(float2*)&H1p[c0 + 2][2 * r] = make_float2(v, v);
        v = tanh_acc(p1.y); *(float2*)&H1p[c0 + 3][2 * r] = make_float2(v, v);
        v = tanh_acc(q0.x); *(float2*)&H1c[c0 + 0][2 * r] = make_float2(v, v);
        v = tanh_acc(q0.y); *(float2*)&H1c[c0 + 1][2 * r] = make_float2(v, v);
        v = tanh_acc(q1.x); *(float2*)&H1c[c0 + 2][2 * r] = make_float2(v, v);
        v = tanh_acc(q1.y); *(float2*)&H1c[c0 + 3][2 * r] = make_float2(v, v);
    }
    __syncthreads();

    // ---- layer 2 (both MLPs): K = 64 ----
    {
        ulonglong2 bp = __ldg((const ulonglong2*)(bp2 + c0));
        ulonglong2 bc = __ldg((const ulonglong2*)(bc2 + c0));
        ap0 = bp.x; ap1 = bp.y; ac0 = bc.x; ac1 = bc.y;
        #pragma unroll 8
        for (int k = 0; k < HID; k++) {
            ull hp2 = *(const ull*)&H1p[k][2 * r];
            ull hc2 = *(const ull*)&H1c[k][2 * r];
            ulonglong2 wp = __ldg((const ulonglong2*)(Wp2 + k * HID + c0));
            ulonglong2 wc = __ldg((const ulonglong2*)(Wc2 + k * HID + c0));
            ap0 = fma2(hp2, wp.x, ap0);
            ap1 = fma2(hp2, wp.y, ap1);
            ac0 = fma2(hc2, wc.x, ac0);
            ac1 = fma2(hc2, wc.y, ac1);
        }
        float2 p0 = unpack2(ap0), p1 = unpack2(ap1);
        float2 q0 = unpack2(ac0), q1 = unpack2(ac1);
        float v;
        v = tanh_acc(p0.x); *(float2*)&H2p[c0 + 0][2 * r] = make_float2(v, v);
        v = tanh_acc(p0.y); *(float2*)&H2p[c0 + 1][2 * r] = make_float2(v, v);
        v = tanh_acc(p1.x); *(float2*)&H2p[c0 + 2][2 * r] = make_float2(v, v);
        v = tanh_acc(p1.y); *(float2*)&H2p[c0 + 3][2 * r] = make_float2(v, v);
        v = tanh_acc(q0.x); *(float2*)&H2c[c0 + 0][2 * r] = make_float2(v, v);
        v = tanh_acc(q0.y); *(float2*)&H2c[c0 + 1][2 * r] = make_float2(v, v);
        v = tanh_acc(q1.x); *(float2*)&H2c[c0 + 2][2 * r] = make_float2(v, v);
        v = tanh_acc(q1.y); *(float2*)&H2c[c0 + 3][2 * r] = make_float2(v, v);
    }
    __syncthreads();

    // ---- parallel: warps 0-1 reduce quadrature; warp 2 does layer 3 ----
    {
        int w = t >> 5, lane = t & 31;
        if (w < 2) {
            #pragma unroll
            for (int a = 2 * w; a < 2 * w + 2; a++) {
                float v = qs[a][lane] + qs[a][lane + 32]
                        + qs[a][lane + 64] + qs[a][lane + 96];
                v += __shfl_xor_sync(0xFFFFFFFF, v, 16);
                v += __shfl_xor_sync(0xFFFFFFFF, v, 8);
                v += __shfl_xor_sync(0xFFFFFFFF, v, 4);
                v += __shfl_xor_sync(0xFFFFFFFF, v, 2);
                v += __shfl_xor_sync(0xFFFFFFFF, v, 1);
                if (lane == 0) qsum[a] = v;
            }
        } else if (t >= 64 && t < 64 + 2 * TILE) {
            int idx = t - 64;
            int mlp = idx >> 3, rr = idx & 7;
            const float* W3 = mlp ? Wc3 : Wp3;
            const float* H2 = mlp ? &H2c[0][0] : &H2p[0][0];
            float s0 = __ldg(mlp ? bc3 : bp3);
            float s1 = 0.f, s2 = 0.f, s3 = 0.f;
            #pragma unroll 4
            for (int k = 0; k < HID; k += 4) {
                s0 = fmaf(H2[(k + 0) * HP2 + 2 * rr], __ldg(W3 + k + 0), s0);
                s1 = fmaf(H2[(k + 1) * HP2 + 2 * rr], __ldg(W3 + k + 1), s1);
                s2 = fmaf(H2[(k + 2) * HP2 + 2 * rr], __ldg(W3 + k + 2), s2);
                s3 = fmaf(H2[(k + 3) * HP2 + 2 * rr], __ldg(W3 + k + 3), s3);
            }
            Ys[mlp][rr] = (s0 + s1) + (s2 + s3);
        }
    }
    __syncthreads();

    // ---- epilogue: MIMICS physics, analytically reduced quadrature ----
    if (t < TILE) {
        int s = base + t;

        float inv = 1.0f / qsum[0];
        float S1 = qsum[1] * inv, S2 = qsum[2] * inv, S3 = qsum[3] * inv;

        float Nb = exp10f(2.0f + 3.0f * sigm(nb_raw[0]));
        float Nl = exp10f(3.0f + 3.0f * sigm(nl_raw[0]));
        float dens = Nb * 1e-4f + Nl * 1e-6f;

        float mg   = 0.05f + 0.75f * sigm(mg_raw[0]);
        float epsv = 1.5f + 20.0f * mg;
        float Kv   = (epsv - 1.0f) / (epsv + 2.0f);
        float Kv2  = Kv * Kv;

        float sm = 0.01f * (0.5f + 5.5f * sigm(s_raw[0]));
        float kw = 2.0f * PI * (5.405e9f / 2.998e8f);
        float tt = 2.0f * kw * sm;
        float c_r = tt * tt;

        float m_v   = 0.93f * sigm(Ys[0][t]);
        float delta = 0.05f * tanh_acc(Ys[1][t]);
        float eps_g = 3.0f + 25.0f * m_v + 10.0f * m_v * m_v;

        float ti = theta[s] * (PI / 180.0f);
        float ct = cosf(ti), st = sinf(ti);
        float ct2 = ct * ct, st2 = st * st;

        float crown_vv = Kv2 * (ct2 * ct2 * S1 + 3.0f * ct2 * st2 * S2
                                + 0.375f * st2 * st2 * S3);
        float crown_vh = Kv2 * (0.5f * ct2 * S2 + 0.125f * st2 * S3);

        float root  = sqrtf(eps_g - st2);
        float r_v   = (eps_g * ct - root) / (eps_g * ct + root);
        float gamma = r_v * r_v;
        float rough = expf(-c_r * ct2);
        float ground = gamma * rough * ct2;

        float svv = dens * crown_vv + ground;
        float svh = dens * crown_vh + 0.05f * ground;

        out[0 * N_TOT + s] = m_v;
        out[1 * N_TOT + s] = delta;
        out[2 * N_TOT + s] = m_v + delta;
        out[3 * N_TOT + s] = 10.0f * log10f(svv + 1e-12f);
        out[4 * N_TOT + s] = 10.0f * log10f(svh + 1e-12f);
        out[5 * N_TOT + s] = eps_g;
    }
}

extern "C" void kernel_launch(void* const* d_in, const int* in_sizes, int n_in,
                              void* d_out, int out_size) {
    // inputs: 0 X, 1 theta_inc_deg, 2 vv_db_observed (unused),
    // 3 Wp1, 4 bp1, 5 Wp2, 6 bp2, 7 Wp3, 8 bp3,
    // 9 Wc1, 10 bc1, 11 Wc2, 12 bc2, 13 Wc3, 14 bc3,
    // 15 nb_raw, 16 nl_raw, 17 so_raw, 18 mg_raw, 19 s_raw
    (void)in_sizes; (void)n_in; (void)out_size;

    pinn_kernel<<<NBLK, NTHR>>>(
        (const float*)d_in[0], (const float*)d_in[1],
        (const float*)d_in[3], (const float*)d_in[4],
        (const float*)d_in[5], (const float*)d_in[6],
        (const float*)d_in[7], (const float*)d_in[8],
        (const float*)d_in[9], (const float*)d_in[10],
        (const float*)d_in[11], (const float*)d_in[12],
        (const float*)d_in[13], (const float*)d_in[14],
        (const float*)d_in[15], (const float*)d_in[16],
        (const float*)d_in[17], (const float*)d_in[18],
        (const float*)d_in[19],
        (float*)d_out);
}

// round 4
// speedup vs baseline: 1.2998x; 1.2998x over previous
#include <cuda_runtime.h>
#include <math.h>

#define N_TOT  8192
#define NF     8
#define HID    64
#define TILE   16
#define NTHR   128
#define NBLK   (N_TOT / TILE)   // 512
#define HP2    (2 * TILE + 2)   // 34: pitch in floats, dup (h,h) pairs

typedef unsigned long long ull;

__device__ __forceinline__ float sigm(float x) {
    return 1.0f / (1.0f + __expf(-x));
}

// Accurate tanh (used only where it feeds an output directly).
__device__ __forceinline__ float tanh_acc(float x) {
    float ax = fabsf(x);
    if (ax < 0.0625f) {
        float x2 = x * x;
        return x * (1.0f + x2 * (-0.33333333f + x2 * 0.13333334f));
    }
    float e = __expf(-2.0f * ax);
    float r = (1.0f - e) / (1.0f + e);
    return (x < 0.0f) ? -r : r;
}

// HW tanh approximation (sm_75+ MUFU.TANH, ~2^-11 accuracy) for hidden layers.
__device__ __forceinline__ float tanha(float x) {
    float r;
    asm("tanh.approx.f32 %0, %1;" : "=f"(r) : "f"(x));
    return r;
}

// Packed dual-lane FMA (sm_103a FFMA2; ptxas never emits this from C++).
__device__ __forceinline__ ull fma2(ull a, ull b, ull c) {
    ull d;
    asm("fma.rn.f32x2 %0, %1, %2, %3;" : "=l"(d) : "l"(a), "l"(b), "l"(c));
    return d;
}
__device__ __forceinline__ float2 unpack2(ull v) {
    float2 r;
    asm("mov.b64 {%0, %1}, %2;" : "=f"(r.x), "=f"(r.y) : "l"(v));
    return r;
}

// ---------------------------------------------------------------------------
// Fused kernel: dual MLP (8->64->64->1) + quadrature reduction + MIMICS
// epilogue. 512 blocks x 128 threads, 16 samples/block.
// Thread microtile: 2 samples x 4 cols x 2 MLPs, FFMA2-packed over col pairs.
// Activations stored duplicated (h,h) in smem -> packed a-operand is 1 LDS.64.
// Per layer-2 k-iter per warp: 2 LDG.128 + 4 LDS.64 + 8 FFMA2 (512 FMAs).
// 128x32 orientation quadrature collapsed analytically to 3 theta-moments
// (exact: uniform 32-pt phi-sum of cos^k, k<=4, equals continuous mean).
// ---------------------------------------------------------------------------
__global__ __launch_bounds__(NTHR)
void pinn_kernel(const float* __restrict__ X,
                 const float* __restrict__ theta,
                 const float* __restrict__ Wp1, const float* __restrict__ bp1,
                 const float* __restrict__ Wp2, const float* __restrict__ bp2,
                 const float* __restrict__ Wp3, const float* __restrict__ bp3,
                 const float* __restrict__ Wc1, const float* __restrict__ bc1,
                 const float* __restrict__ Wc2, const float* __restrict__ bc2,
                 const float* __restrict__ Wc3, const float* __restrict__ bc3,
                 const float* __restrict__ nb_raw, const float* __restrict__ nl_raw,
                 const float* __restrict__ so_raw, const float* __restrict__ mg_raw,
                 const float* __restrict__ s_raw,
                 float* __restrict__ out) {
    __shared__ float XT2[NF][HP2];                  // duplicated (x,x)
    __shared__ float H1p[HID][HP2], H1c[HID][HP2];  // duplicated (h,h)
    __shared__ float H2p[HID][HP2], H2c[HID][HP2];
    __shared__ float qs[4][NTHR];
    __shared__ float qsum[4];
    __shared__ float Ys[2][TILE];

    const int t = threadIdx.x;
    const int base = blockIdx.x * TILE;
    const float PI = 3.14159265358979f;

    // ---- stage: quadrature point per thread + X (duplicated) ----
    {
        float sig_o = (10.0f + 70.0f * sigm(so_raw[0])) * (PI / 180.0f);
        float th  = (float)t * (PI * 0.5f / 127.0f);   // linspace(0, pi/2, 128)
        float d   = th - PI * 0.25f;
        float pdf = expf(-d * d / (2.0f * sig_o * sig_o)) * sinf(th);
        float c = cosf(th), s = sinf(th);
        float c2 = c * c, s2 = s * s;
        qs[0][t] = pdf;
        qs[1][t] = pdf * c2 * c2;
        qs[2][t] = pdf * c2 * s2;
        qs[3][t] = pdf * s2 * s2;
    }
    {   // 128 elements, one per thread, contiguous
        int r = t >> 3, k = t & 7;
        float x = X[base * NF + t];
        *(float2*)&XT2[k][2 * r] = make_float2(x, x);
    }
    __syncthreads();

    const int c0 = (t & 15) * 4;       // 4 hidden cols owned
    const int s0 = (t >> 4) * 2;       // first of 2 samples owned

    // packed accumulators: [sample][colpair] for MLP p and c
    ull ap00, ap01, ap10, ap11, ac00, ac01, ac10, ac11;

    // ---- layer 1 (both MLPs): K = 8 ----
    {
        ulonglong2 bp = __ldg((const ulonglong2*)(bp1 + c0));
        ulonglong2 bc = __ldg((const ulonglong2*)(bc1 + c0));
        ap00 = bp.x; ap01 = bp.y; ap10 = bp.x; ap11 = bp.y;
        ac00 = bc.x; ac01 = bc.y; ac10 = bc.x; ac11 = bc.y;
        #pragma unroll
        for (int k = 0; k < NF; k++) {
            ull x0 = *(const ull*)&XT2[k][2 * s0];
            ull x1 = *(const ull*)&XT2[k][2 * s0 + 2];
            ulonglong2 wp = __ldg((const ulonglong2*)(Wp1 + k * HID + c0));
            ulonglong2 wc = __ldg((const ulonglong2*)(Wc1 + k * HID + c0));
            ap00 = fma2(x0, wp.x, ap00); ap01 = fma2(x0, wp.y, ap01);
            ap10 = fma2(x1, wp.x, ap10); ap11 = fma2(x1, wp.y, ap11);
            ac00 = fma2(x0, wc.x, ac00); ac01 = fma2(x0, wc.y, ac01);
            ac10 = fma2(x1, wc.x, ac10); ac11 = fma2(x1, wc.y, ac11);
        }
        float2 v;  float h;
        v = unpack2(ap00);
        h = tanha(v.x); *(float2*)&H1p[c0 + 0][2 * s0] = make_float2(h, h);
        h = tanha(v.y); *(float2*)&H1p[c0 + 1][2 * s0] = make_float2(h, h);
        v = unpack2(ap01);
        h = tanha(v.x); *(float2*)&H1p[c0 + 2][2 * s0] = make_float2(h, h);
        h = tanha(v.y); *(float2*)&H1p[c0 + 3][2 * s0] = make_float2(h, h);
        v = unpack2(ap10);
        h = tanha(v.x); *(float2*)&H1p[c0 + 0][2 * s0 + 2] = make_float2(h, h);
        h = tanha(v.y); *(float2*)&H1p[c0 + 1][2 * s0 + 2] = make_float2(h, h);
        v = unpack2(ap11);
        h = tanha(v.x); *(float2*)&H1p[c0 + 2][2 * s0 + 2] = make_float2(h, h);
        h = tanha(v.y); *(float2*)&H1p[c0 + 3][2 * s0 + 2] = make_float2(h, h);
        v = unpack2(ac00);
        h = tanha(v.x); *(float2*)&H1c[c0 + 0][2 * s0] = make_float2(h, h);
        h = tanha(v.y); *(float2*)&H1c[c0 + 1][2 * s0] = make_float2(h, h);
        v = unpack2(ac01);
        h = tanha(v.x); *(float2*)&H1c[c0 + 2][2 * s0] = make_float2(h, h);
        h = tanha(v.y); *(float2*)&H1c[c0 + 3][2 * s0] = make_float2(h, h);
        v = unpack2(ac10);
        h = tanha(v.x); *(float2*)&H1c[c0 + 0][2 * s0 + 2] = make_float2(h, h);
        h = tanha(v.y); *(float2*)&H1c[c0 + 1][2 * s0 + 2] = make_float2(h, h);
        v = unpack2(ac11);
        h = tanha(v.x); *(float2*)&H1c[c0 + 2][2 * s0 + 2] = make_float2(h, h);
        h = tanha(v.y); *(float2*)&H1c[c0 + 3][2 * s0 + 2] = make_float2(h, h);
    }
    __syncthreads();

    // ---- layer 2 (both MLPs): K = 64 ----
    {
        ulonglong2 bp = __ldg((const ulonglong2*)(bp2 + c0));
        ulonglong2 bc = __ldg((const ulonglong2*)(bc2 + c0));
        ap00 = bp.x; ap01 = bp.y; ap10 = bp.x; ap11 = bp.y;
        ac00 = bc.x; ac01 = bc.y; ac10 = bc.x; ac11 = bc.y;
        #pragma unroll 8
        for (int k = 0; k < HID; k++) {
            ull hp0 = *(const ull*)&H1p[k][2 * s0];
            ull hp1 = *(const ull*)&H1p[k][2 * s0 + 2];
            ull hc0 = *(const ull*)&H1c[k][2 * s0];
            ull hc1 = *(const ull*)&H1c[k][2 * s0 + 2];
            ulonglong2 wp = __ldg((const ulonglong2*)(Wp2 + k * HID + c0));
            ulonglong2 wc = __ldg((const ulonglong2*)(Wc2 + k * HID + c0));
            ap00 = fma2(hp0, wp.x, ap00); ap01 = fma2(hp0, wp.y, ap01);
            ap10 = fma2(hp1, wp.x, ap10); ap11 = fma2(hp1, wp.y, ap11);
            ac00 = fma2(hc0, wc.x, ac00); ac01 = fma2(hc0, wc.y, ac01);
            ac10 = fma2(hc1, wc.x, ac10); ac11 = fma2(hc1, wc.y, ac11);
        }
        float2 v;  float h;
        v = unpack2(ap00);
        h = tanha(v.x); *(float2*)&H2p[c0 + 0][2 * s0] = make_float2(h, h);
        h = tanha(v.y); *(float2*)&H2p[c0 + 1][2 * s0] = make_float2(h, h);
        v = unpack2(ap01);
        h = tanha(v.x); *(float2*)&H2p[c0 + 2][2 * s0] = make_float2(h, h);
        h = tanha(v.y); *(float2*)&H2p[c0 + 3][2 * s0] = make_float2(h, h);
        v = unpack2(ap10);
        h = tanha(v.x); *(float2*)&H2p[c0 + 0][2 * s0 + 2] = make_float2(h, h);
        h = tanha(v.y); *(float2*)&H2p[c0 + 1][2 * s0 + 2] = make_float2(h, h);
        v = unpack2(ap11);
        h = tanha(v.x); *(float2*)&H2p[c0 + 2][2 * s0 + 2] = make_float2(h, h);
        h = tanha(v.y); *(float2*)&H2p[c0 + 3][2 * s0 + 2] = make_float2(h, h);
        v = unpack2(ac00);
        h = tanha(v.x); *(float2*)&H2c[c0 + 0][2 * s0] = make_float2(h, h);
        h = tanha(v.y); *(float2*)&H2c[c0 + 1][2 * s0] = make_float2(h, h);
        v = unpack2(ac01);
        h = tanha(v.x); *(float2*)&H2c[c0 + 2][2 * s0] = make_float2(h, h);
        h = tanha(v.y); *(float2*)&H2c[c0 + 3][2 * s0] = make_float2(h, h);
        v = unpack2(ac10);
        h = tanha(v.x); *(float2*)&H2c[c0 + 0][2 * s0 + 2] = make_float2(h, h);
        h = tanha(v.y); *(float2*)&H2c[c0 + 1][2 * s0 + 2] = make_float2(h, h);
        v = unpack2(ac11);
        h = tanha(v.x); *(float2*)&H2c[c0 + 2][2 * s0 + 2] = make_float2(h, h);
        h = tanha(v.y); *(float2*)&H2c[c0 + 3][2 * s0 + 2] = make_float2(h, h);
    }
    __syncthreads();

    // ---- parallel: warps 0-1 reduce quadrature; warp 2 does layer 3 ----
    {
        int w = t >> 5, lane = t & 31;
        if (w < 2) {
            #pragma unroll
            for (int a = 2 * w; a < 2 * w + 2; a++) {
                float v = qs[a][lane] + qs[a][lane + 32]
                        + qs[a][lane + 64] + qs[a][lane + 96];
                v += __shfl_xor_sync(0xFFFFFFFF, v, 16);
                v += __shfl_xor_sync(0xFFFFFFFF, v, 8);
                v += __shfl_xor_sync(0xFFFFFFFF, v, 4);
                v += __shfl_xor_sync(0xFFFFFFFF, v, 2);
                v += __shfl_xor_sync(0xFFFFFFFF, v, 1);
                if (lane == 0) qsum[a] = v;
            }
        } else if (w == 2) {
            int idx = t - 64;                  // 0..31
            int mlp = idx >> 4, rr = idx & 15; // 2 MLPs x 16 samples
            const float* W3 = mlp ? Wc3 : Wp3;
            const float* H2 = mlp ? &H2c[0][0] : &H2p[0][0];
            float v0 = __ldg(mlp ? bc3 : bp3);
            float v1 = 0.f, v2 = 0.f, v3 = 0.f;
            #pragma unroll 4
            for (int k = 0; k < HID; k += 4) {
                v0 = fmaf(H2[(k + 0) * HP2 + 2 * rr], __ldg(W3 + k + 0), v0);
                v1 = fmaf(H2[(k + 1) * HP2 + 2 * rr], __ldg(W3 + k + 1), v1);
                v2 = fmaf(H2[(k + 2) * HP2 + 2 * rr], __ldg(W3 + k + 2), v2);
                v3 = fmaf(H2[(k + 3) * HP2 + 2 * rr], __ldg(W3 + k + 3), v3);
            }
            Ys[mlp][rr] = (v0 + v1) + (v2 + v3);
        }
    }
    __syncthreads();

    // ---- epilogue: MIMICS physics, analytically reduced quadrature ----
    if (t < TILE) {
        int s = base + t;

        float inv = 1.0f / qsum[0];
        float S1 = qsum[1] * inv, S2 = qsum[2] * inv, S3 = qsum[3] * inv;

        float Nb = exp10f(2.0f + 3.0f * sigm(nb_raw[0]));
        float Nl = exp10f(3.0f + 3.0f * sigm(nl_raw[0]));
        float dens = Nb * 1e-4f + Nl * 1e-6f;

        float mg   = 0.05f + 0.75f * sigm(mg_raw[0]);
        float epsv = 1.5f + 20.0f * mg;
        float Kv   = (epsv - 1.0f) / (epsv + 2.0f);
        float Kv2  = Kv * Kv;

        float sm = 0.01f * (0.5f + 5.5f * sigm(s_raw[0]));
        float kw = 2.0f * PI * (5.405e9f / 2.998e8f);
        float tt = 2.0f * kw * sm;
        float c_r = tt * tt;

        float m_v   = 0.93f * sigm(Ys[0][t]);
        float delta = 0.05f * tanh_acc(Ys[1][t]);   // direct output: exact tanh
        float eps_g = 3.0f + 25.0f * m_v + 10.0f * m_v * m_v;

        float ti = theta[s] * (PI / 180.0f);
        float ct = cosf(ti), st = sinf(ti);
        float ct2 = ct * ct, st2 = st * st;

        float crown_vv = Kv2 * (ct2 * ct2 * S1 + 3.0f * ct2 * st2 * S2
                                + 0.375f * st2 * st2 * S3);
        float crown_vh = Kv2 * (0.5f * ct2 * S2 + 0.125f * st2 * S3);

        float root  = sqrtf(eps_g - st2);
        float r_v   = (eps_g * ct - root) / (eps_g * ct + root);
        float gamma = r_v * r_v;
        float rough = expf(-c_r * ct2);
        float ground = gamma * rough * ct2;

        float svv = dens * crown_vv + ground;
        float svh = dens * crown_vh + 0.05f * ground;

        out[0 * N_TOT + s] = m_v;
        out[1 * N_TOT + s] = delta;
        out[2 * N_TOT + s] = m_v + delta;
        out[3 * N_TOT + s] = 10.0f * log10f(svv + 1e-12f);
        out[4 * N_TOT + s] = 10.0f * log10f(svh + 1e-12f);
        out[5 * N_TOT + s] = eps_g;
    }
}

extern "C" void kernel_launch(void* const* d_in, const int* in_sizes, int n_in,
                              void* d_out, int out_size) {
    // inputs: 0 X, 1 theta_inc_deg, 2 vv_db_observed (unused),
    // 3 Wp1, 4 bp1, 5 Wp2, 6 bp2, 7 Wp3, 8 bp3,
    // 9 Wc1, 10 bc1, 11 Wc2, 12 bc2, 13 Wc3, 14 bc3,
    // 15 nb_raw, 16 nl_raw, 17 so_raw, 18 mg_raw, 19 s_raw
    (void)in_sizes; (void)n_in; (void)out_size;

    pinn_kernel<<<NBLK, NTHR>>>(
        (const float*)d_in[0], (const float*)d_in[1],
        (const float*)d_in[3], (const float*)d_in[4],
        (const float*)d_in[5], (const float*)d_in[6],
        (const float*)d_in[7], (const float*)d_in[8],
        (const float*)d_in[9], (const float*)d_in[10],
        (const float*)d_in[11], (const float*)d_in[12],
        (const float*)d_in[13], (const float*)d_in[14],
        (const float*)d_in[15], (const float*)d_in[16],
        (const float*)d_in[17], (const float*)d_in[18],
        (const float*)d_in[19],
        (float*)d_out);
}